// round 10
// baseline (speedup 1.0000x reference)
#include <cuda_runtime.h>
#include <math_constants.h>

// Problem constants (from reference setup_inputs)
#define BATCH   8
#define NPTS    4096
#define NSLOT   (2 * BATCH)          // 16 point clouds (x and y per batch)
#define TOTPTS  (NSLOT * NPTS)       // 65536

// Uniform grid over [-4.5, 4.5]^3 (points are N(0,1)^3; |coord| < 4.5 whp,
// outliers are clamped to edge cells, which is bound-safe: clamping only
// moves a point's cell CLOSER to queries than its true position, so the
// "unscanned cells are >= r*h away" lower bound still holds).
#define GD      32
#define GC      (GD * GD * GD)       // 32768 cells
#define GRID_MIN  (-4.5f)
#define GRID_H    (9.0f / (float)GD)     // 0.28125
#define GRID_INVH ((float)GD / 9.0f)

#define QBLK    256
#define NQBLK   (TOTPTS / QBLK)      // 256 query blocks
#define ZCHUNK  (NSLOT * GC / NQBLK) // 2048 counts zeroed per query block

#define PBLK    64                   // partial-reduce blocks
#define PTHR    256

// Scratch (no allocs). Replay invariant: g_counts is zero at kernel_launch
// entry (static zero-init on load; re-zeroed by query_kernel each call).
// Everything else is fully overwritten before being read, every call.
__device__ int    g_counts[NSLOT * GC];
__device__ int    g_starts[NSLOT * GC];   // within-slot exclusive prefix
__device__ int    g_cursor[NSLOT * GC];   // scatter cursor; post-scatter = cell ends
__device__ float4 g_sorted[TOTPTS];       // (x, y, z, bitcast original id)
__device__ float  g_res[TOTPTS];          // per-original-point NN distance
__device__ float  g_partial[PBLK];

__device__ __forceinline__ int cell_of(float v) {
    int i = (int)floorf((v - GRID_MIN) * GRID_INVH);
    return min(max(i, 0), GD - 1);
}

__device__ __forceinline__ const float* point_ptr(const float* x, const float* y,
                                                  int gid) {
    int s = gid >> 12;           // slot = b*2 + cloud
    int n = gid & (NPTS - 1);
    int b = s >> 1;
    const float* src = (s & 1) ? y : x;
    return src + ((size_t)b * NPTS + n) * 3;
}

// 1) Histogram points into cells.
__global__ __launch_bounds__(256)
void count_kernel(const float* __restrict__ x, const float* __restrict__ y) {
    int gid = blockIdx.x * 256 + threadIdx.x;
    const float* p = point_ptr(x, y, gid);
    int cell = (cell_of(p[2]) * GD + cell_of(p[1])) * GD + cell_of(p[0]);
    atomicAdd(&g_counts[(gid >> 12) * GC + cell], 1);
}

// 2) Per-slot exclusive prefix scan over the 32768 cell counts.
__global__ __launch_bounds__(1024)
void scan_kernel() {
    __shared__ int sh[1024];
    const int s = blockIdx.x;
    const int t = threadIdx.x;
    const int base = s * GC + t * 32;

    int sum = 0;
#pragma unroll
    for (int i = 0; i < 32; i++) sum += g_counts[base + i];
    sh[t] = sum;
    __syncthreads();
    for (int off = 1; off < 1024; off <<= 1) {
        int v = (t >= off) ? sh[t - off] : 0;
        __syncthreads();
        sh[t] += v;
        __syncthreads();
    }
    int run = sh[t] - sum;   // exclusive offset of this thread's 32-cell chunk
#pragma unroll
    for (int i = 0; i < 32; i++) {
        int c = g_counts[base + i];
        g_starts[base + i] = run;
        g_cursor[base + i] = run;
        run += c;
    }
}

// 3) Scatter points into cell-sorted order; stash original id in .w.
__global__ __launch_bounds__(256)
void scatter_kernel(const float* __restrict__ x, const float* __restrict__ y) {
    int gid = blockIdx.x * 256 + threadIdx.x;
    int s = gid >> 12;
    const float* p = point_ptr(x, y, gid);
    float px = p[0], py = p[1], pz = p[2];
    int cell = (cell_of(pz) * GD + cell_of(py)) * GD + cell_of(px);
    int pos = atomicAdd(&g_cursor[s * GC + cell], 1);   // within-slot position
    g_sorted[s * NPTS + pos] = make_float4(px, py, pz, __int_as_float(gid));
}

// 4) Exact NN via expanding Chebyshev rings. Queries iterate in cell-sorted
// order (warp-coherent). Also re-zeros g_counts for the next graph replay
// (query never reads counts -> race-free).
__global__ __launch_bounds__(QBLK)
void query_kernel() {
    const int q  = blockIdx.x * QBLK + threadIdx.x;
    const int s  = q >> 12;
    const int ts = s ^ 1;                 // target cloud: same batch, other set

    float4 pp = g_sorted[q];
    const int orig = __float_as_int(pp.w);
    const int cx = cell_of(pp.x), cy = cell_of(pp.y), cz = cell_of(pp.z);

    const int*    __restrict__ tst = g_starts + ts * GC;
    const int*    __restrict__ ten = g_cursor + ts * GC;
    const float4* __restrict__ tp  = g_sorted + ts * NPTS;

    float best = CUDART_INF_F;
    for (int r = 1; r < GD; r++) {
        // Scan cube radius r; for r>1 skip the already-scanned cube r-1.
        int z0 = max(cz - r, 0), z1 = min(cz + r, GD - 1);
        int y0 = max(cy - r, 0), y1 = min(cy + r, GD - 1);
        int x0 = max(cx - r, 0), x1 = min(cx + r, GD - 1);
        for (int iz = z0; iz <= z1; iz++) {
            int az = abs(iz - cz);
            for (int iy = y0; iy <= y1; iy++) {
                int ay = max(az, abs(iy - cy));
                int rowbase = (iz * GD + iy) * GD;
                for (int ix = x0; ix <= x1; ix++) {
                    if (r > 1 && max(ay, abs(ix - cx)) < r) continue;
                    int cell = rowbase + ix;
                    int t0 = tst[cell], t1 = ten[cell];
                    for (int tt = t0; tt < t1; tt++) {
                        float4 qq = tp[tt];
                        float dx = pp.x - qq.x;
                        float dy = pp.y - qq.y;
                        float dz = pp.z - qq.z;
                        best = fminf(best, fmaf(dz, dz, fmaf(dy, dy, dx * dx)));
                    }
                }
            }
        }
        // All unscanned cells are >= r*h away (conservative, clamp-safe).
        float clr = (float)r * GRID_H;
        if (best <= clr * clr) break;
    }

    g_res[orig] = sqrtf(best);

    // Reset counts slice for the next replay.
    const int zb = blockIdx.x * ZCHUNK;
    for (int j = threadIdx.x; j < ZCHUNK; j += QBLK) g_counts[zb + j] = 0;
}

// 5) Fixed-order partial sums over g_res (deterministic output).
__global__ __launch_bounds__(PTHR)
void partial_kernel() {
    __shared__ float sh[PTHR];
    const int base = blockIdx.x * (TOTPTS / PBLK) + threadIdx.x;
    float v = 0.0f;
#pragma unroll
    for (int r = 0; r < TOTPTS / PBLK / PTHR; r++) v += g_res[base + r * PTHR];
    sh[threadIdx.x] = v;
    __syncthreads();
    for (int off = PTHR / 2; off > 0; off >>= 1) {
        if (threadIdx.x < off) sh[threadIdx.x] += sh[threadIdx.x + off];
        __syncthreads();
    }
    if (threadIdx.x == 0) g_partial[blockIdx.x] = sh[0];
}

// 6) Final fold.
__global__ __launch_bounds__(64)
void final_kernel(float* __restrict__ out) {
    __shared__ float sh[64];
    sh[threadIdx.x] = g_partial[threadIdx.x];
    __syncthreads();
    for (int off = 32; off > 0; off >>= 1) {
        if (threadIdx.x < off) sh[threadIdx.x] += sh[threadIdx.x + off];
        __syncthreads();
    }
    if (threadIdx.x == 0) out[0] = sh[0] / (float)(BATCH * NPTS);
}

extern "C" void kernel_launch(void* const* d_in, const int* in_sizes, int n_in,
                              void* d_out, int out_size) {
    const float* x = (const float*)d_in[0];
    const float* y = (const float*)d_in[1];
    float* out = (float*)d_out;

    count_kernel<<<TOTPTS / 256, 256>>>(x, y);
    scan_kernel<<<NSLOT, 1024>>>();
    scatter_kernel<<<TOTPTS / 256, 256>>>(x, y);
    query_kernel<<<NQBLK, QBLK>>>();
    partial_kernel<<<PBLK, PTHR>>>();
    final_kernel<<<1, 64>>>(out);
}

// round 13
// speedup vs baseline: 2.0668x; 2.0668x over previous
#include <cuda_runtime.h>
#include <math_constants.h>

// Problem constants (from reference setup_inputs)
#define BATCH   8
#define NPTS    4096
#define NSLOT   (2 * BATCH)          // 16 point clouds (x and y per batch)
#define TOTPTS  (NSLOT * NPTS)       // 65536

// Uniform grid over [-4.5, 4.5]^3. Outliers clamp to edge cells (bound-safe:
// clamping only moves cells closer together, so the "unscanned cells are
// >= r*h away" lower bound still holds).
#define GD      32
#define GC      (GD * GD * GD)       // 32768 cells
#define GRID_MIN  (-4.5f)
#define GRID_H    (9.0f / (float)GD)     // 0.28125
#define GRID_INVH ((float)GD / 9.0f)

#define QBLK    128
#define NQBLK   (TOTPTS / QBLK)      // 512 query blocks
#define ZCHUNK  (NSLOT * GC / NQBLK) // 1024 counts zeroed per query block

#define PBLK    64                   // partial-reduce blocks
#define PTHR    256

// Scratch (no allocs). Replay invariant: g_counts is zero at kernel_launch
// entry (static zero-init on load; re-zeroed by query_kernel each call).
// Everything else is fully overwritten before being read, every call.
__device__ int    g_counts[NSLOT * GC];
__device__ int    g_starts[NSLOT * GC];   // within-slot exclusive prefix
__device__ int    g_cursor[NSLOT * GC];   // scatter cursor; post-scatter = cell ends
__device__ float4 g_sorted[TOTPTS];       // (x, y, z, bitcast original id)
__device__ float  g_res[TOTPTS];          // per-original-point NN distance
__device__ float  g_partial[PBLK];

__device__ __forceinline__ int cell_of(float v) {
    int i = (int)floorf((v - GRID_MIN) * GRID_INVH);
    return min(max(i, 0), GD - 1);
}

__device__ __forceinline__ const float* point_ptr(const float* x, const float* y,
                                                  int gid) {
    int s = gid >> 12;           // slot = b*2 + cloud
    int n = gid & (NPTS - 1);
    int b = s >> 1;
    const float* src = (s & 1) ? y : x;
    return src + ((size_t)b * NPTS + n) * 3;
}

// Scan candidates [t0, t1) against pp, folding into best.
__device__ __forceinline__ void scan_range(const float4* __restrict__ tp,
                                           int t0, int t1, float4 pp,
                                           float& best) {
    for (int t = t0; t < t1; t++) {
        float4 qq = tp[t];
        float dx = pp.x - qq.x;
        float dy = pp.y - qq.y;
        float dz = pp.z - qq.z;
        best = fminf(best, fmaf(dz, dz, fmaf(dy, dy, dx * dx)));
    }
}

// 1) Histogram points into cells.
__global__ __launch_bounds__(256)
void count_kernel(const float* __restrict__ x, const float* __restrict__ y) {
    int gid = blockIdx.x * 256 + threadIdx.x;
    const float* p = point_ptr(x, y, gid);
    int cell = (cell_of(p[2]) * GD + cell_of(p[1])) * GD + cell_of(p[0]);
    atomicAdd(&g_counts[(gid >> 12) * GC + cell], 1);
}

// 2) Per-slot exclusive prefix scan over the 32768 cell counts.
__global__ __launch_bounds__(1024)
void scan_kernel() {
    __shared__ int sh[1024];
    const int s = blockIdx.x;
    const int t = threadIdx.x;
    const int base = s * GC + t * 32;

    int sum = 0;
#pragma unroll
    for (int i = 0; i < 32; i++) sum += g_counts[base + i];
    sh[t] = sum;
    __syncthreads();
    for (int off = 1; off < 1024; off <<= 1) {
        int v = (t >= off) ? sh[t - off] : 0;
        __syncthreads();
        sh[t] += v;
        __syncthreads();
    }
    int run = sh[t] - sum;   // exclusive offset of this thread's 32-cell chunk
#pragma unroll
    for (int i = 0; i < 32; i++) {
        int c = g_counts[base + i];
        g_starts[base + i] = run;
        g_cursor[base + i] = run;
        run += c;
    }
}

// 3) Scatter points into cell-sorted order; stash original id in .w.
__global__ __launch_bounds__(256)
void scatter_kernel(const float* __restrict__ x, const float* __restrict__ y) {
    int gid = blockIdx.x * 256 + threadIdx.x;
    int s = gid >> 12;
    const float* p = point_ptr(x, y, gid);
    float px = p[0], py = p[1], pz = p[2];
    int cell = (cell_of(pz) * GD + cell_of(py)) * GD + cell_of(px);
    int pos = atomicAdd(&g_cursor[s * GC + cell], 1);   // within-slot position
    g_sorted[s * NPTS + pos] = make_float4(px, py, pz, __int_as_float(gid));
}

// 4) Exact NN. Ring 1 scans 9 CONTIGUOUS row-ranges (cells (iz,iy,cx-1..cx+1)
// are consecutive in sorted order) with all 18 range loads batched up-front
// for MLP. Rare r>=2 passes scan only the shell. Queries iterate in
// cell-sorted order (warp-coherent; tail queries cluster in the same warps).
// Also re-zeros g_counts for the next graph replay (race-free: query never
// reads counts).
__global__ __launch_bounds__(QBLK)
void query_kernel() {
    const int q  = blockIdx.x * QBLK + threadIdx.x;
    const int s  = q >> 12;
    const int ts = s ^ 1;                 // target cloud: same batch, other set

    float4 pp = g_sorted[q];
    const int orig = __float_as_int(pp.w);
    const int cx = cell_of(pp.x), cy = cell_of(pp.y), cz = cell_of(pp.z);

    const int*    __restrict__ tst = g_starts + ts * GC;
    const int*    __restrict__ ten = g_cursor + ts * GC;
    const float4* __restrict__ tp  = g_sorted + ts * NPTS;

    float best = CUDART_INF_F;

    // ---- Ring 0+1: cube radius 1 as 9 contiguous row ranges, batched. ----
    {
        const int x0 = max(cx - 1, 0), x1 = min(cx + 1, GD - 1);
        int rt0[9], rt1[9];
#pragma unroll
        for (int k = 0; k < 9; k++) {
            int iz = cz + k / 3 - 1;
            int iy = cy + k % 3 - 1;
            if (iz >= 0 && iz < GD && iy >= 0 && iy < GD) {
                int rb = (iz * GD + iy) * GD;
                rt0[k] = __ldg(&tst[rb + x0]);
                rt1[k] = __ldg(&ten[rb + x1]);
            } else {
                rt0[k] = 0;
                rt1[k] = 0;
            }
        }
#pragma unroll
        for (int k = 0; k < 9; k++) {
            scan_range(tp, rt0[k], rt1[k], pp, best);
        }
    }

    // ---- Rare expansion: scan only the SHELL at radius r. ----
    float lim = GRID_H;                   // unscanned cells >= 1*h away
    for (int r = 2; best > lim * lim && r < GD; r++) {
        int z0 = max(cz - r, 0), z1 = min(cz + r, GD - 1);
        int y0 = max(cy - r, 0), y1 = min(cy + r, GD - 1);
        int x0 = max(cx - r, 0), x1 = min(cx + r, GD - 1);
        for (int iz = z0; iz <= z1; iz++) {
            int az = abs(iz - cz);
            for (int iy = y0; iy <= y1; iy++) {
                int rb = (iz * GD + iy) * GD;
                if (az == r || abs(iy - cy) == r) {
                    // edge row: full contiguous range
                    scan_range(tp, __ldg(&tst[rb + x0]), __ldg(&ten[rb + x1]),
                               pp, best);
                } else {
                    // interior row: only the two x = cx +/- r cells
                    if (cx - r >= 0) {
                        int c = rb + cx - r;
                        scan_range(tp, __ldg(&tst[c]), __ldg(&ten[c]), pp, best);
                    }
                    if (cx + r < GD) {
                        int c = rb + cx + r;
                        scan_range(tp, __ldg(&tst[c]), __ldg(&ten[c]), pp, best);
                    }
                }
            }
        }
        lim = (float)r * GRID_H;
    }

    g_res[orig] = sqrtf(best);

    // Reset counts slice for the next replay.
    const int zb = blockIdx.x * ZCHUNK;
    for (int j = threadIdx.x; j < ZCHUNK; j += QBLK) g_counts[zb + j] = 0;
}

// 5) Fixed-order partial sums over g_res (deterministic output).
__global__ __launch_bounds__(PTHR)
void partial_kernel() {
    __shared__ float sh[PTHR];
    const int base = blockIdx.x * (TOTPTS / PBLK) + threadIdx.x;
    float v = 0.0f;
#pragma unroll
    for (int r = 0; r < TOTPTS / PBLK / PTHR; r++) v += g_res[base + r * PTHR];
    sh[threadIdx.x] = v;
    __syncthreads();
    for (int off = PTHR / 2; off > 0; off >>= 1) {
        if (threadIdx.x < off) sh[threadIdx.x] += sh[threadIdx.x + off];
        __syncthreads();
    }
    if (threadIdx.x == 0) g_partial[blockIdx.x] = sh[0];
}

// 6) Final fold.
__global__ __launch_bounds__(64)
void final_kernel(float* __restrict__ out) {
    __shared__ float sh[64];
    sh[threadIdx.x] = g_partial[threadIdx.x];
    __syncthreads();
    for (int off = 32; off > 0; off >>= 1) {
        if (threadIdx.x < off) sh[threadIdx.x] += sh[threadIdx.x + off];
        __syncthreads();
    }
    if (threadIdx.x == 0) out[0] = sh[0] / (float)(BATCH * NPTS);
}

extern "C" void kernel_launch(void* const* d_in, const int* in_sizes, int n_in,
                              void* d_out, int out_size) {
    const float* x = (const float*)d_in[0];
    const float* y = (const float*)d_in[1];
    float* out = (float*)d_out;

    count_kernel<<<TOTPTS / 256, 256>>>(x, y);
    scan_kernel<<<NSLOT, 1024>>>();
    scatter_kernel<<<TOTPTS / 256, 256>>>(x, y);
    query_kernel<<<NQBLK, QBLK>>>();
    partial_kernel<<<PBLK, PTHR>>>();
    final_kernel<<<1, 64>>>(out);
}

// round 14
// speedup vs baseline: 5.5992x; 2.7091x over previous
#include <cuda_runtime.h>
#include <math_constants.h>

// Problem constants (from reference setup_inputs)
#define BATCH   8
#define NPTS    4096
#define NSLOT   (2 * BATCH)          // 16 point clouds (x and y per batch)
#define TOTPTS  (NSLOT * NPTS)       // 65536

// Uniform grid over [-4.5, 4.5]^3. Outliers clamp to edge cells (bound-safe).
#define GD      32
#define GC      (GD * GD * GD)       // 32768 cells
#define NCELLS  (NSLOT * GC)         // 524288
#define GRID_MIN  (-4.5f)
#define GRID_H    (9.0f / (float)GD)     // 0.28125
#define GRID_INVH ((float)GD / 9.0f)

// Scan phases
#define SB      512                  // scan blocks
#define SCT     (NCELLS / SB)        // 1024 cells per scan block (32 blocks/slot)
#define STH     256                  // threads per scan block (4 cells/thread)

// Query: 4 threads (a "quad") per query
#define QTHR    256
#define NQBLK   (TOTPTS * 4 / QTHR)  // 1024 blocks
#define ZCHUNK  (NCELLS / NQBLK)     // 512 counts zeroed per query block

#define PBLK    64
#define PTHR    256

// Scratch (no allocs). Replay invariant: g_counts is zero at kernel_launch
// entry (static zero-init; re-zeroed by query_kernel each call). Everything
// else is fully overwritten before being read, every call.
__device__ int    g_counts[NCELLS];
__device__ int    g_blksum[SB];
__device__ int    g_blkoff[SB];
__device__ int    g_starts[NCELLS];
__device__ int    g_cursor[NCELLS];
__device__ float4 g_sorted[TOTPTS];       // (x, y, z, bitcast original id)
__device__ float  g_res[TOTPTS];
__device__ float  g_partial[PBLK];

__device__ __forceinline__ int cell_of(float v) {
    int i = (int)floorf((v - GRID_MIN) * GRID_INVH);
    return min(max(i, 0), GD - 1);
}

__device__ __forceinline__ const float* point_ptr(const float* x, const float* y,
                                                  int gid) {
    int s = gid >> 12;
    int n = gid & (NPTS - 1);
    int b = s >> 1;
    const float* src = (s & 1) ? y : x;
    return src + ((size_t)b * NPTS + n) * 3;
}

__device__ __forceinline__ void scan_range(const float4* __restrict__ tp,
                                           int t0, int t1, float4 pp,
                                           float& best) {
    for (int t = t0; t < t1; t++) {
        float4 qq = tp[t];
        float dx = pp.x - qq.x;
        float dy = pp.y - qq.y;
        float dz = pp.z - qq.z;
        best = fminf(best, fmaf(dz, dz, fmaf(dy, dy, dx * dx)));
    }
}

// 1) Histogram points into cells.
__global__ __launch_bounds__(256)
void count_kernel(const float* __restrict__ x, const float* __restrict__ y) {
    int gid = blockIdx.x * 256 + threadIdx.x;
    const float* p = point_ptr(x, y, gid);
    int cell = (cell_of(p[2]) * GD + cell_of(p[1])) * GD + cell_of(p[0]);
    atomicAdd(&g_counts[(gid >> 12) * GC + cell], 1);
}

// 2a) Per-scan-block sums (coalesced int4 loads).
__global__ __launch_bounds__(STH)
void scan_sum_kernel() {
    __shared__ int sh[STH];
    const int t = threadIdx.x;
    const int4 c = ((const int4*)g_counts)[blockIdx.x * STH + t];
    sh[t] = c.x + c.y + c.z + c.w;
    __syncthreads();
    for (int off = STH / 2; off > 0; off >>= 1) {
        if (t < off) sh[t] += sh[t + off];
        __syncthreads();
    }
    if (t == 0) g_blksum[blockIdx.x] = sh[0];
}

// 2b) Segmented exclusive scan of the 512 block sums. Segment = 32 blocks
// (= one slot) = exactly one warp -> pure warp shfl scan.
__global__ __launch_bounds__(SB)
void scan_mid_kernel() {
    const int t = threadIdx.x;
    const int lane = t & 31;
    int v = g_blksum[t];
    int incl = v;
#pragma unroll
    for (int off = 1; off < 32; off <<= 1) {
        int u = __shfl_up_sync(0xFFFFFFFFu, incl, off);
        if (lane >= off) incl += u;
    }
    g_blkoff[t] = incl - v;   // exclusive within slot
}

// 2c) Final prefixes: block-local scan of 1024 counts + block offset.
__global__ __launch_bounds__(STH)
void scan_fin_kernel() {
    __shared__ int wsum[STH / 32];
    const int t = threadIdx.x;
    const int lane = t & 31;
    const int w = t >> 5;

    const int4 c = ((const int4*)g_counts)[blockIdx.x * STH + t];
    int tsum = c.x + c.y + c.z + c.w;

    int incl = tsum;
#pragma unroll
    for (int off = 1; off < 32; off <<= 1) {
        int u = __shfl_up_sync(0xFFFFFFFFu, incl, off);
        if (lane >= off) incl += u;
    }
    if (lane == 31) wsum[w] = incl;
    __syncthreads();
    int woff = 0;
    for (int i = 0; i < w; i++) woff += wsum[i];   // 8 warps: cheap serial
    int base = g_blkoff[blockIdx.x] + woff + (incl - tsum);

    int4 st;
    st.x = base;
    st.y = base + c.x;
    st.z = base + c.x + c.y;
    st.w = base + c.x + c.y + c.z;
    ((int4*)g_starts)[blockIdx.x * STH + t] = st;
    ((int4*)g_cursor)[blockIdx.x * STH + t] = st;
}

// 3) Scatter points into cell-sorted order; stash original id in .w.
__global__ __launch_bounds__(256)
void scatter_kernel(const float* __restrict__ x, const float* __restrict__ y) {
    int gid = blockIdx.x * 256 + threadIdx.x;
    int s = gid >> 12;
    const float* p = point_ptr(x, y, gid);
    float px = p[0], py = p[1], pz = p[2];
    int cell = (cell_of(pz) * GD + cell_of(py)) * GD + cell_of(px);
    int pos = atomicAdd(&g_cursor[s * GC + cell], 1);
    g_sorted[s * NPTS + pos] = make_float4(px, py, pz, __int_as_float(gid));
}

// 4) Exact NN, 4 threads per query. Ring 1: 9 contiguous row ranges strided
// across the quad, combined with 2 quad-shfls. Rare r>=2 shells also strided
// across the quad with a per-round combine (termination uniform in-quad).
// Also re-zeros g_counts for the next replay (query never reads counts).
__global__ __launch_bounds__(QTHR)
void query_kernel() {
    const int gt   = blockIdx.x * QTHR + threadIdx.x;
    const int q    = gt >> 2;            // sorted query position
    const int quad = gt & 3;
    const unsigned qmask = 0xFu << ((threadIdx.x & 31) & ~3);

    const int s  = q >> 12;
    const int ts = s ^ 1;

    float4 pp = g_sorted[q];
    const int orig = __float_as_int(pp.w);
    const int cx = cell_of(pp.x), cy = cell_of(pp.y), cz = cell_of(pp.z);

    const int*    __restrict__ tst = g_starts + ts * GC;
    const int*    __restrict__ ten = g_cursor + ts * GC;
    const float4* __restrict__ tp  = g_sorted + ts * NPTS;

    float best = CUDART_INF_F;

    // ---- Ring 0+1: rows k = quad, quad+4, quad+8 (k < 9), ranges batched. --
    {
        const int x0 = max(cx - 1, 0), x1 = min(cx + 1, GD - 1);
        int rt0[3], rt1[3];
        int nr = 0;
#pragma unroll
        for (int kk = 0; kk < 3; kk++) {
            int k = quad + 4 * kk;
            if (k < 9) {
                int iz = cz + k / 3 - 1;
                int iy = cy + k % 3 - 1;
                if (iz >= 0 && iz < GD && iy >= 0 && iy < GD) {
                    int rb = (iz * GD + iy) * GD;
                    rt0[nr] = __ldg(&tst[rb + x0]);
                    rt1[nr] = __ldg(&ten[rb + x1]);
                } else {
                    rt0[nr] = 0;
                    rt1[nr] = 0;
                }
                nr++;
            }
        }
        for (int i = 0; i < nr; i++) scan_range(tp, rt0[i], rt1[i], pp, best);

        best = fminf(best, __shfl_xor_sync(qmask, best, 1));
        best = fminf(best, __shfl_xor_sync(qmask, best, 2));
    }

    // ---- Rare expansion: shell rows strided across the quad. ----
    float lim = GRID_H;
    for (int r = 2; best > lim * lim && r < GD; r++) {
        int z0 = max(cz - r, 0), z1 = min(cz + r, GD - 1);
        int y0 = max(cy - r, 0), y1 = min(cy + r, GD - 1);
        int x0 = max(cx - r, 0), x1 = min(cx + r, GD - 1);
        int ny = y1 - y0 + 1;
        int nrows = (z1 - z0 + 1) * ny;
        for (int idx = quad; idx < nrows; idx += 4) {
            int iz = z0 + idx / ny;
            int iy = y0 + idx % ny;
            int rb = (iz * GD + iy) * GD;
            if (abs(iz - cz) == r || abs(iy - cy) == r) {
                scan_range(tp, __ldg(&tst[rb + x0]), __ldg(&ten[rb + x1]),
                           pp, best);
            } else {
                if (cx - r >= 0) {
                    int c = rb + cx - r;
                    scan_range(tp, __ldg(&tst[c]), __ldg(&ten[c]), pp, best);
                }
                if (cx + r < GD) {
                    int c = rb + cx + r;
                    scan_range(tp, __ldg(&tst[c]), __ldg(&ten[c]), pp, best);
                }
            }
        }
        best = fminf(best, __shfl_xor_sync(qmask, best, 1));
        best = fminf(best, __shfl_xor_sync(qmask, best, 2));
        lim = (float)r * GRID_H;
    }

    if (quad == 0) g_res[orig] = sqrtf(best);

    // Reset counts slice for the next replay (int4 stores).
    {
        int4* zp = (int4*)g_counts + blockIdx.x * (ZCHUNK / 4);
        const int4 z4 = make_int4(0, 0, 0, 0);
        for (int j = threadIdx.x; j < ZCHUNK / 4; j += QTHR) zp[j] = z4;
    }
}

// 5) Fixed-order partial sums over g_res (deterministic output).
__global__ __launch_bounds__(PTHR)
void partial_kernel() {
    __shared__ float sh[PTHR];
    const int base = blockIdx.x * (TOTPTS / PBLK) + threadIdx.x;
    float v = 0.0f;
#pragma unroll
    for (int r = 0; r < TOTPTS / PBLK / PTHR; r++) v += g_res[base + r * PTHR];
    sh[threadIdx.x] = v;
    __syncthreads();
    for (int off = PTHR / 2; off > 0; off >>= 1) {
        if (threadIdx.x < off) sh[threadIdx.x] += sh[threadIdx.x + off];
        __syncthreads();
    }
    if (threadIdx.x == 0) g_partial[blockIdx.x] = sh[0];
}

// 6) Final fold.
__global__ __launch_bounds__(64)
void final_kernel(float* __restrict__ out) {
    __shared__ float sh[64];
    sh[threadIdx.x] = g_partial[threadIdx.x];
    __syncthreads();
    for (int off = 32; off > 0; off >>= 1) {
        if (threadIdx.x < off) sh[threadIdx.x] += sh[threadIdx.x + off];
        __syncthreads();
    }
    if (threadIdx.x == 0) out[0] = sh[0] / (float)(BATCH * NPTS);
}

extern "C" void kernel_launch(void* const* d_in, const int* in_sizes, int n_in,
                              void* d_out, int out_size) {
    const float* x = (const float*)d_in[0];
    const float* y = (const float*)d_in[1];
    float* out = (float*)d_out;

    count_kernel<<<TOTPTS / 256, 256>>>(x, y);
    scan_sum_kernel<<<SB, STH>>>();
    scan_mid_kernel<<<1, SB>>>();
    scan_fin_kernel<<<SB, STH>>>();
    scatter_kernel<<<TOTPTS / 256, 256>>>(x, y);
    query_kernel<<<NQBLK, QTHR>>>();
    partial_kernel<<<PBLK, PTHR>>>();
    final_kernel<<<1, 64>>>(out);
}

// round 15
// speedup vs baseline: 6.0000x; 1.0716x over previous
#include <cuda_runtime.h>
#include <math_constants.h>

// Problem constants (from reference setup_inputs)
#define BATCH   8
#define NPTS    4096
#define NSLOT   (2 * BATCH)          // 16 point clouds (x and y per batch)
#define TOTPTS  (NSLOT * NPTS)       // 65536

// Uniform grid over [-4.5, 4.5]^3, GD=20 (h=0.45, ~5-6 pts/cell).
// Outliers clamp to edge cells (bound-safe: clamped points are farther than
// their cell suggests, so the ">= r*h" lower bound still holds).
#define GD      20
#define GC      (GD * GD * GD)       // 8000 real cells
#define GSTRIDE 8192                 // padded per-slot stride (pad cells = 0)
#define NCELLS  (NSLOT * GSTRIDE)    // 131072
#define GRID_MIN  (-4.5f)
#define GRID_H    (9.0f / (float)GD)     // 0.45
#define GRID_INVH ((float)GD / 9.0f)

// Coalesced 3-phase scan: 128 blocks x 256 threads x int4 = 131072 cells.
#define SB      128                  // scan blocks (8 per slot)
#define STH     256

// Query: 1 thread per query (ranges now long enough to pipeline).
#define QTHR    128
#define NQBLK   (TOTPTS / QTHR)      // 512 blocks
#define ZCHUNK  (NCELLS / NQBLK)     // 256 counts zeroed per query block

#define PBLK    64
#define PTHR    256

// Scratch (no allocs). Replay invariant: g_counts is zero at kernel_launch
// entry (static zero-init; re-zeroed by query_kernel each call). Everything
// else is fully overwritten before being read, every call.
__device__ int    g_counts[NCELLS];
__device__ int    g_blksum[SB];
__device__ int    g_blkoff[SB];
__device__ int    g_starts[NCELLS];
__device__ int    g_cursor[NCELLS];
__device__ float4 g_sorted[TOTPTS];       // (x, y, z, bitcast original id)
__device__ float  g_res[TOTPTS];
__device__ float  g_partial[PBLK];

__device__ __forceinline__ int cell_of(float v) {
    int i = (int)floorf((v - GRID_MIN) * GRID_INVH);
    return min(max(i, 0), GD - 1);
}

__device__ __forceinline__ const float* point_ptr(const float* x, const float* y,
                                                  int gid) {
    int s = gid >> 12;
    int n = gid & (NPTS - 1);
    int b = s >> 1;
    const float* src = (s & 1) ? y : x;
    return src + ((size_t)b * NPTS + n) * 3;
}

__device__ __forceinline__ void scan_range(const float4* __restrict__ tp,
                                           int t0, int t1, float4 pp,
                                           float& best) {
#pragma unroll 4
    for (int t = t0; t < t1; t++) {
        float4 qq = tp[t];
        float dx = pp.x - qq.x;
        float dy = pp.y - qq.y;
        float dz = pp.z - qq.z;
        best = fminf(best, fmaf(dz, dz, fmaf(dy, dy, dx * dx)));
    }
}

// 1) Histogram points into cells.
__global__ __launch_bounds__(256)
void count_kernel(const float* __restrict__ x, const float* __restrict__ y) {
    int gid = blockIdx.x * 256 + threadIdx.x;
    const float* p = point_ptr(x, y, gid);
    int cell = (cell_of(p[2]) * GD + cell_of(p[1])) * GD + cell_of(p[0]);
    atomicAdd(&g_counts[(gid >> 12) * GSTRIDE + cell], 1);
}

// 2a) Per-scan-block sums (coalesced int4 loads).
__global__ __launch_bounds__(STH)
void scan_sum_kernel() {
    __shared__ int sh[STH];
    const int t = threadIdx.x;
    const int4 c = ((const int4*)g_counts)[blockIdx.x * STH + t];
    sh[t] = c.x + c.y + c.z + c.w;
    __syncthreads();
    for (int off = STH / 2; off > 0; off >>= 1) {
        if (t < off) sh[t] += sh[t + off];
        __syncthreads();
    }
    if (t == 0) g_blksum[blockIdx.x] = sh[0];
}

// 2b) Segmented exclusive scan of the 128 block sums; segment = 8 blocks
// (= one slot), aligned within warps -> shfl with width 8.
__global__ __launch_bounds__(SB)
void scan_mid_kernel() {
    const int t = threadIdx.x;
    const int lane = t & 7;
    int v = g_blksum[t];
    int incl = v;
#pragma unroll
    for (int off = 1; off < 8; off <<= 1) {
        int u = __shfl_up_sync(0xFFFFFFFFu, incl, off, 8);
        if (lane >= off) incl += u;
    }
    g_blkoff[t] = incl - v;   // exclusive within slot
}

// 2c) Final prefixes: block-local scan of 1024 counts + block offset.
__global__ __launch_bounds__(STH)
void scan_fin_kernel() {
    __shared__ int wsum[STH / 32];
    const int t = threadIdx.x;
    const int lane = t & 31;
    const int w = t >> 5;

    const int4 c = ((const int4*)g_counts)[blockIdx.x * STH + t];
    int tsum = c.x + c.y + c.z + c.w;

    int incl = tsum;
#pragma unroll
    for (int off = 1; off < 32; off <<= 1) {
        int u = __shfl_up_sync(0xFFFFFFFFu, incl, off);
        if (lane >= off) incl += u;
    }
    if (lane == 31) wsum[w] = incl;
    __syncthreads();
    int woff = 0;
    for (int i = 0; i < w; i++) woff += wsum[i];
    int base = g_blkoff[blockIdx.x] + woff + (incl - tsum);

    int4 st;
    st.x = base;
    st.y = base + c.x;
    st.z = base + c.x + c.y;
    st.w = base + c.x + c.y + c.z;
    ((int4*)g_starts)[blockIdx.x * STH + t] = st;
    ((int4*)g_cursor)[blockIdx.x * STH + t] = st;
}

// 3) Scatter points into cell-sorted order; stash original id in .w.
__global__ __launch_bounds__(256)
void scatter_kernel(const float* __restrict__ x, const float* __restrict__ y) {
    int gid = blockIdx.x * 256 + threadIdx.x;
    int s = gid >> 12;
    const float* p = point_ptr(x, y, gid);
    float px = p[0], py = p[1], pz = p[2];
    int cell = (cell_of(pz) * GD + cell_of(py)) * GD + cell_of(px);
    int pos = atomicAdd(&g_cursor[s * GSTRIDE + cell], 1);  // within-slot pos
    g_sorted[s * NPTS + pos] = make_float4(px, py, pz, __int_as_float(gid));
}

// 4) Exact NN, 1 thread per query. Ring 1 = 9 contiguous row-ranges
// (~17 points each at GD=20) with all 18 range loads batched up-front;
// the long inner loops pipeline (unroll 4). Rare r>=2 passes scan only the
// shell. Queries iterate in cell-sorted order (warp-coherent; neighbors hit
// the same rows -> L1 reuse). Also re-zeros g_counts for the next replay.
__global__ __launch_bounds__(QTHR)
void query_kernel() {
    const int q  = blockIdx.x * QTHR + threadIdx.x;
    const int s  = q >> 12;
    const int ts = s ^ 1;                 // target cloud: same batch, other set

    float4 pp = g_sorted[q];
    const int orig = __float_as_int(pp.w);
    const int cx = cell_of(pp.x), cy = cell_of(pp.y), cz = cell_of(pp.z);

    const int*    __restrict__ tst = g_starts + ts * GSTRIDE;
    const int*    __restrict__ ten = g_cursor + ts * GSTRIDE;
    const float4* __restrict__ tp  = g_sorted + ts * NPTS;

    float best = CUDART_INF_F;

    // ---- Ring 0+1: cube radius 1 as 9 contiguous row ranges, batched. ----
    {
        const int x0 = max(cx - 1, 0), x1 = min(cx + 1, GD - 1);
        int rt0[9], rt1[9];
#pragma unroll
        for (int k = 0; k < 9; k++) {
            int iz = cz + k / 3 - 1;
            int iy = cy + k % 3 - 1;
            if (iz >= 0 && iz < GD && iy >= 0 && iy < GD) {
                int rb = (iz * GD + iy) * GD;
                rt0[k] = __ldg(&tst[rb + x0]);
                rt1[k] = __ldg(&ten[rb + x1]);
            } else {
                rt0[k] = 0;
                rt1[k] = 0;
            }
        }
#pragma unroll
        for (int k = 0; k < 9; k++) {
            scan_range(tp, rt0[k], rt1[k], pp, best);
        }
    }

    // ---- Rare expansion: scan only the SHELL at radius r. ----
    float lim = GRID_H;                   // unscanned cells >= 1*h away
    for (int r = 2; best > lim * lim && r < GD; r++) {
        int z0 = max(cz - r, 0), z1 = min(cz + r, GD - 1);
        int y0 = max(cy - r, 0), y1 = min(cy + r, GD - 1);
        int x0 = max(cx - r, 0), x1 = min(cx + r, GD - 1);
        for (int iz = z0; iz <= z1; iz++) {
            int az = abs(iz - cz);
            for (int iy = y0; iy <= y1; iy++) {
                int rb = (iz * GD + iy) * GD;
                if (az == r || abs(iy - cy) == r) {
                    scan_range(tp, __ldg(&tst[rb + x0]), __ldg(&ten[rb + x1]),
                               pp, best);
                } else {
                    if (cx - r >= 0) {
                        int c = rb + cx - r;
                        scan_range(tp, __ldg(&tst[c]), __ldg(&ten[c]), pp, best);
                    }
                    if (cx + r < GD) {
                        int c = rb + cx + r;
                        scan_range(tp, __ldg(&tst[c]), __ldg(&ten[c]), pp, best);
                    }
                }
            }
        }
        lim = (float)r * GRID_H;
    }

    g_res[orig] = sqrtf(best);

    // Reset counts slice for the next replay (int4 stores).
    {
        int4* zp = (int4*)g_counts + blockIdx.x * (ZCHUNK / 4);
        const int4 z4 = make_int4(0, 0, 0, 0);
        for (int j = threadIdx.x; j < ZCHUNK / 4; j += QTHR) zp[j] = z4;
    }
}

// 5) Fixed-order partial sums over g_res (deterministic output).
__global__ __launch_bounds__(PTHR)
void partial_kernel() {
    __shared__ float sh[PTHR];
    const int base = blockIdx.x * (TOTPTS / PBLK) + threadIdx.x;
    float v = 0.0f;
#pragma unroll
    for (int r = 0; r < TOTPTS / PBLK / PTHR; r++) v += g_res[base + r * PTHR];
    sh[threadIdx.x] = v;
    __syncthreads();
    for (int off = PTHR / 2; off > 0; off >>= 1) {
        if (threadIdx.x < off) sh[threadIdx.x] += sh[threadIdx.x + off];
        __syncthreads();
    }
    if (threadIdx.x == 0) g_partial[blockIdx.x] = sh[0];
}

// 6) Final fold.
__global__ __launch_bounds__(64)
void final_kernel(float* __restrict__ out) {
    __shared__ float sh[64];
    sh[threadIdx.x] = g_partial[threadIdx.x];
    __syncthreads();
    for (int off = 32; off > 0; off >>= 1) {
        if (threadIdx.x < off) sh[threadIdx.x] += sh[threadIdx.x + off];
        __syncthreads();
    }
    if (threadIdx.x == 0) out[0] = sh[0] / (float)(BATCH * NPTS);
}

extern "C" void kernel_launch(void* const* d_in, const int* in_sizes, int n_in,
                              void* d_out, int out_size) {
    const float* x = (const float*)d_in[0];
    const float* y = (const float*)d_in[1];
    float* out = (float*)d_out;

    count_kernel<<<TOTPTS / 256, 256>>>(x, y);
    scan_sum_kernel<<<SB, STH>>>();
    scan_mid_kernel<<<1, SB>>>();
    scan_fin_kernel<<<SB, STH>>>();
    scatter_kernel<<<TOTPTS / 256, 256>>>(x, y);
    query_kernel<<<NQBLK, QTHR>>>();
    partial_kernel<<<PBLK, PTHR>>>();
    final_kernel<<<1, 64>>>(out);
}